// round 1
// baseline (speedup 1.0000x reference)
#include <cuda_runtime.h>
#include <cuda_bf16.h>
#include <math.h>

#define NN 100000
#define EE 1600000

// ---------------- scratch (device globals; no allocation allowed) ----------
__device__ __align__(256) float g_feat[NN * 64];
__device__ __align__(256) float g_res1[NN * 64];
__device__ __align__(256) float g_h1  [NN * 64];
__device__ __align__(256) float g_acc [NN * 64];
__device__ __align__(256) float g_el  [NN * 4];
__device__ __align__(256) float g_er  [NN * 4];
__device__ __align__(256) float g_den [NN * 4];
__device__ __align__(256) float g_w   [EE * 4];

// ---------------- fp32 GEMM: C[n,64] = X[n,K] @ W[K,64] --------------------
// 64 rows x 64 cols per block, 256 threads, K chunked by 64 through smem.
__global__ void gemm64(const float* __restrict__ X, const float* __restrict__ W,
                       float* __restrict__ C, int n, int K) {
    __shared__ float Xs[64 * 68];   // transposed: Xs[k][r], stride 68
    __shared__ float Ws[64 * 68];   // Ws[k][c], stride 68
    const int t = threadIdx.x;
    const int row0 = blockIdx.x * 64;
    const int rr = (t >> 4) << 2;   // 4 rows
    const int cc = (t & 15) << 2;   // 4 cols
    float acc[4][4] = {};

    for (int k0 = 0; k0 < K; k0 += 64) {
        #pragma unroll
        for (int i = t; i < 64 * 64; i += 256) {
            int k = i >> 6, c = i & 63;
            Ws[k * 68 + c] = W[(k0 + k) * 64 + c];
        }
        #pragma unroll
        for (int i = t; i < 64 * 64; i += 256) {
            int r = i >> 6, k = i & 63;
            int gr = row0 + r;
            Xs[k * 68 + r] = (gr < n) ? X[gr * K + k0 + k] : 0.0f;
        }
        __syncthreads();
        #pragma unroll 8
        for (int k = 0; k < 64; k++) {
            float4 a = *(const float4*)&Xs[k * 68 + rr];
            float4 b = *(const float4*)&Ws[k * 68 + cc];
            acc[0][0] += a.x * b.x; acc[0][1] += a.x * b.y; acc[0][2] += a.x * b.z; acc[0][3] += a.x * b.w;
            acc[1][0] += a.y * b.x; acc[1][1] += a.y * b.y; acc[1][2] += a.y * b.z; acc[1][3] += a.y * b.w;
            acc[2][0] += a.z * b.x; acc[2][1] += a.z * b.y; acc[2][2] += a.z * b.z; acc[2][3] += a.z * b.w;
            acc[3][0] += a.w * b.x; acc[3][1] += a.w * b.y; acc[3][2] += a.w * b.z; acc[3][3] += a.w * b.w;
        }
        __syncthreads();
    }
    #pragma unroll
    for (int i = 0; i < 4; i++) {
        int r = row0 + rr + i;
        if (r < n) {
            float4 v = make_float4(acc[i][0], acc[i][1], acc[i][2], acc[i][3]);
            *(float4*)&C[r * 64 + cc] = v;
        }
    }
}

// ---------------- per-node attention logits: el/er --------------------------
__global__ void compute_elr(const float* __restrict__ feat,
                            const float* __restrict__ al, const float* __restrict__ ar,
                            float* __restrict__ el, float* __restrict__ er) {
    int i = blockIdx.x * blockDim.x + threadIdx.x;   // n*4 + h
    if (i >= NN * 4) return;
    int h = i & 3;
    int n = i >> 2;
    const float4* f = (const float4*)(feat + n * 64 + h * 16);
    const float4* a = (const float4*)(al + h * 16);
    const float4* b = (const float4*)(ar + h * 16);
    float s1 = 0.f, s2 = 0.f;
    #pragma unroll
    for (int j = 0; j < 4; j++) {
        float4 fv = f[j], av = a[j], bv = b[j];
        s1 += fv.x * av.x + fv.y * av.y + fv.z * av.z + fv.w * av.w;
        s2 += fv.x * bv.x + fv.y * bv.y + fv.z * bv.z + fv.w * bv.w;
    }
    el[i] = s1;
    er[i] = s2;
}

// ---------------- zero den + acc --------------------------------------------
__global__ void zero_den_acc(float* __restrict__ den, float* __restrict__ acc) {
    int i = blockIdx.x * blockDim.x + threadIdx.x;
    if (i < NN * 64) acc[i] = 0.0f;
    if (i < NN * 4)  den[i] = 0.0f;
}

__device__ __forceinline__ void red_add_v4(float* p, float a, float b, float c, float d) {
    asm volatile("red.global.add.v4.f32 [%0], {%1, %2, %3, %4};"
                 :: "l"(p), "f"(a), "f"(b), "f"(c), "f"(d) : "memory");
}

// ---------------- edge pass 1: exp(leakyrelu(el[s]+er[d])), den += ----------
__global__ void edge_softmax_num(const int* __restrict__ src, const int* __restrict__ dst,
                                 const float* __restrict__ el, const float* __restrict__ er,
                                 float* __restrict__ w, float* __restrict__ den) {
    int e = blockIdx.x * blockDim.x + threadIdx.x;
    if (e >= EE) return;
    int s = src[e], d = dst[e];
    float4 a = __ldg((const float4*)(el + s * 4));
    float4 b = __ldg((const float4*)(er + d * 4));
    float v0 = a.x + b.x, v1 = a.y + b.y, v2 = a.z + b.z, v3 = a.w + b.w;
    v0 = (v0 > 0.f) ? v0 : 0.2f * v0;
    v1 = (v1 > 0.f) ? v1 : 0.2f * v1;
    v2 = (v2 > 0.f) ? v2 : 0.2f * v2;
    v3 = (v3 > 0.f) ? v3 : 0.2f * v3;
    float w0 = __expf(v0), w1 = __expf(v1), w2 = __expf(v2), w3 = __expf(v3);
    *(float4*)(w + e * 4) = make_float4(w0, w1, w2, w3);
    red_add_v4(den + d * 4, w0, w1, w2, w3);
}

// ---------------- reciprocal of denominator ---------------------------------
__global__ void recip_den(float* __restrict__ den) {
    int i = blockIdx.x * blockDim.x + threadIdx.x;
    if (i < NN * 4) den[i] = 1.0f / den[i];
}

// ---------------- edge pass 2: acc[dst] += alpha * feat[src] ----------------
// 16 threads per edge; thread j handles 4 floats (head = j/4).
__global__ void edge_aggregate(const int* __restrict__ src, const int* __restrict__ dst,
                               const float* __restrict__ w, const float* __restrict__ rden,
                               const float* __restrict__ feat, float* __restrict__ acc) {
    long long gid = (long long)blockIdx.x * blockDim.x + threadIdx.x;
    int e = (int)(gid >> 4);
    if (e >= EE) return;
    int j = (int)(gid & 15);
    int s = __ldg(src + e), d = __ldg(dst + e);
    int h = j >> 2;
    float alpha = __ldg(w + e * 4 + h) * __ldg(rden + d * 4 + h);
    float4 f = __ldg((const float4*)(feat + s * 64 + j * 4));
    red_add_v4(acc + d * 64 + j * 4, alpha * f.x, alpha * f.y, alpha * f.z, alpha * f.w);
}

// ---------------- layer-1 epilogue: h1 = elu(acc + res1 + b1) ---------------
__global__ void epilogue1(const float* __restrict__ acc, const float* __restrict__ res1,
                          const float* __restrict__ b1, float* __restrict__ h1) {
    int i = blockIdx.x * blockDim.x + threadIdx.x;
    if (i >= NN * 64) return;
    float v = acc[i] + res1[i] + __ldg(b1 + (i & 63));
    h1[i] = (v > 0.f) ? v : expm1f(v);
}

// ---------------- layer-2 epilogue: out = mean_h(acc + h1 + b2) -------------
__global__ void epilogue2(const float* __restrict__ acc, const float* __restrict__ h1,
                          const float* __restrict__ b2, float* __restrict__ out) {
    int i = blockIdx.x * blockDim.x + threadIdx.x;   // n*16 + d
    if (i >= NN * 16) return;
    int n = i >> 4, dd = i & 15;
    float s = 0.f;
    #pragma unroll
    for (int h = 0; h < 4; h++) {
        int k = n * 64 + h * 16 + dd;
        s += acc[k] + h1[k] + __ldg(b2 + h * 16 + dd);
    }
    out[i] = 0.25f * s;
}

// ---------------- launch -----------------------------------------------------
extern "C" void kernel_launch(void* const* d_in, const int* in_sizes, int n_in,
                              void* d_out, int out_size) {
    const float* x     = (const float*)d_in[0];
    const int*   src   = (const int*)  d_in[1];
    const int*   dst   = (const int*)  d_in[2];
    const float* W1    = (const float*)d_in[3];
    const float* al1   = (const float*)d_in[4];
    const float* ar1   = (const float*)d_in[5];
    const float* resW1 = (const float*)d_in[6];
    const float* b1    = (const float*)d_in[7];
    const float* W2    = (const float*)d_in[8];
    const float* al2   = (const float*)d_in[9];
    const float* ar2   = (const float*)d_in[10];
    const float* b2    = (const float*)d_in[11];
    float* out = (float*)d_out;

    float *feat, *res1, *h1, *acc, *el, *er, *den, *w;
    cudaGetSymbolAddress((void**)&feat, g_feat);
    cudaGetSymbolAddress((void**)&res1, g_res1);
    cudaGetSymbolAddress((void**)&h1,   g_h1);
    cudaGetSymbolAddress((void**)&acc,  g_acc);
    cudaGetSymbolAddress((void**)&el,   g_el);
    cudaGetSymbolAddress((void**)&er,   g_er);
    cudaGetSymbolAddress((void**)&den,  g_den);
    cudaGetSymbolAddress((void**)&w,    g_w);

    const int T = 256;
    const int gemmBlocks = (NN + 63) / 64;           // 1563
    const int elrBlocks  = (NN * 4 + T - 1) / T;     // 1563
    const int zeroBlocks = (NN * 64 + T - 1) / T;    // 25000
    const int edgeBlocks = (EE + T - 1) / T;         // 6250
    const int aggBlocks  = (EE * 16 + T - 1) / T;    // 100000
    const int epi1Blocks = (NN * 64 + T - 1) / T;    // 25000
    const int epi2Blocks = (NN * 16 + T - 1) / T;    // 6250

    // ---- layer 1 ----
    gemm64<<<gemmBlocks, T>>>(x, W1,    feat, NN, 128);
    gemm64<<<gemmBlocks, T>>>(x, resW1, res1, NN, 128);
    compute_elr<<<elrBlocks, T>>>(feat, al1, ar1, el, er);
    zero_den_acc<<<zeroBlocks, T>>>(den, acc);
    edge_softmax_num<<<edgeBlocks, T>>>(src, dst, el, er, w, den);
    recip_den<<<elrBlocks, T>>>(den);
    edge_aggregate<<<aggBlocks, T>>>(src, dst, w, den, feat, acc);
    epilogue1<<<epi1Blocks, T>>>(acc, res1, b1, h1);

    // ---- layer 2 ----
    gemm64<<<gemmBlocks, T>>>(h1, W2, feat, NN, 64);
    compute_elr<<<elrBlocks, T>>>(feat, al2, ar2, el, er);
    zero_den_acc<<<zeroBlocks, T>>>(den, acc);
    edge_softmax_num<<<edgeBlocks, T>>>(src, dst, el, er, w, den);
    recip_den<<<elrBlocks, T>>>(den);
    edge_aggregate<<<aggBlocks, T>>>(src, dst, w, den, feat, acc);
    epilogue2<<<epi2Blocks, T>>>(acc, h1, b2, out);
}

// round 2
// speedup vs baseline: 1.7417x; 1.7417x over previous
#include <cuda_runtime.h>
#include <cuda_bf16.h>
#include <math.h>

#define NN 100000
#define EE 1600000
#define NB 98           // ceil(NN/1024)

// ---------------- scratch (device globals; no allocation allowed) ----------
__device__ __align__(256) float g_feat[NN * 64];
__device__ __align__(256) float g_res1[NN * 64];
__device__ __align__(256) float g_h1  [NN * 64];
__device__ __align__(256) float g_el  [NN * 4];
__device__ __align__(256) float g_er  [NN * 4];
__device__ __align__(256) int   g_cnt [NN];
__device__ __align__(256) int   g_rowptr[NN + 1];
__device__ __align__(256) int   g_cursor[NN];
__device__ __align__(256) int   g_csrc[EE];
__device__ __align__(256) int   g_bsum[NB];
__device__ __align__(256) int   g_boff[NB];

// =================== CSR build ==============================================
__global__ void zero_cnt(int* __restrict__ cnt) {
    int i = blockIdx.x * blockDim.x + threadIdx.x;
    if (i < NN) cnt[i] = 0;
}

__global__ void hist_dst(const int* __restrict__ dst, int* __restrict__ cnt) {
    int e = blockIdx.x * blockDim.x + threadIdx.x;
    if (e < EE) atomicAdd(cnt + dst[e], 1);
}

// per-block sums of cnt (1024 per block)
__global__ void block_sums(const int* __restrict__ cnt, int* __restrict__ bsum) {
    __shared__ int wsum[32];
    int t = threadIdx.x;
    int i = blockIdx.x * 1024 + t;
    int v = (i < NN) ? cnt[i] : 0;
    #pragma unroll
    for (int o = 16; o > 0; o >>= 1) v += __shfl_down_sync(~0u, v, o);
    if ((t & 31) == 0) wsum[t >> 5] = v;
    __syncthreads();
    if (t < 32) {
        int s = wsum[t];
        #pragma unroll
        for (int o = 16; o > 0; o >>= 1) s += __shfl_down_sync(~0u, s, o);
        if (t == 0) bsum[blockIdx.x] = s;
    }
}

// exclusive scan of NB block sums (single block, 128 threads)
__global__ void scan_bsums(const int* __restrict__ bsum, int* __restrict__ boff) {
    __shared__ int buf[128];
    int t = threadIdx.x;
    int v = (t < NB) ? bsum[t] : 0;
    buf[t] = v;
    __syncthreads();
    #pragma unroll
    for (int o = 1; o < 128; o <<= 1) {
        int x = (t >= o) ? buf[t - o] : 0;
        __syncthreads();
        buf[t] += x;
        __syncthreads();
    }
    if (t < NB) boff[t] = buf[t] - v;   // exclusive
}

// block-local inclusive scan + block offset -> rowptr / cursor
__global__ void scan_final(const int* __restrict__ cnt, const int* __restrict__ boff,
                           int* __restrict__ rowptr, int* __restrict__ cursor) {
    __shared__ int wsum[32];
    int t = threadIdx.x;
    int i = blockIdx.x * 1024 + t;
    int v = (i < NN) ? cnt[i] : 0;
    int lane = t & 31, wid = t >> 5;
    int x = v;
    #pragma unroll
    for (int o = 1; o < 32; o <<= 1) {
        int y = __shfl_up_sync(~0u, x, o);
        if (lane >= o) x += y;
    }
    if (lane == 31) wsum[wid] = x;
    __syncthreads();
    if (wid == 0) {
        int s = wsum[lane];
        #pragma unroll
        for (int o = 1; o < 32; o <<= 1) {
            int y = __shfl_up_sync(~0u, s, o);
            if (lane >= o) s += y;
        }
        wsum[lane] = s;
    }
    __syncthreads();
    int incl = x + ((wid > 0) ? wsum[wid - 1] : 0) + boff[blockIdx.x];
    if (i < NN) {
        rowptr[i + 1] = incl;
        cursor[i] = incl - v;
    }
    if (i == 0) rowptr[0] = 0;
}

__global__ void scatter_edges(const int* __restrict__ src, const int* __restrict__ dst,
                              int* __restrict__ cursor, int* __restrict__ csrc) {
    int e = blockIdx.x * blockDim.x + threadIdx.x;
    if (e >= EE) return;
    int pos = atomicAdd(cursor + dst[e], 1);
    csrc[pos] = src[e];
}

// =================== fp32 GEMM: C[n,64] = X[n,K] @ W[K,64] ==================
// 128x64 tile, 128 threads, 8x8 register blocking.
__global__ void __launch_bounds__(128) gemm128x64(
        const float* __restrict__ X, const float* __restrict__ W,
        float* __restrict__ C, int n, int K) {
    __shared__ float Xs[64][132];   // [k][row]
    __shared__ float Ws[64][68];    // [k][col]
    const int t = threadIdx.x;
    const int row0 = blockIdx.x * 128;
    const int tr = (t >> 3) * 8;    // rows tr..tr+7
    const int tc = (t & 7) * 8;     // cols tc..tc+7
    float acc[8][8] = {};

    for (int k0 = 0; k0 < K; k0 += 64) {
        // W tile: 64x64 floats = 1024 float4
        #pragma unroll
        for (int i = t; i < 1024; i += 128) {
            int k = i >> 4, c = (i & 15) * 4;
            float4 wv = *(const float4*)&W[(k0 + k) * 64 + c];
            Ws[k][c] = wv.x; Ws[k][c + 1] = wv.y; Ws[k][c + 2] = wv.z; Ws[k][c + 3] = wv.w;
        }
        // X tile transposed: 128 rows x 64 k = 2048 float4
        #pragma unroll
        for (int i = t; i < 2048; i += 128) {
            int r = i >> 4, k = (i & 15) * 4;
            int gr = row0 + r;
            float4 xv = (gr < n) ? *(const float4*)&X[gr * K + k0 + k]
                                 : make_float4(0.f, 0.f, 0.f, 0.f);
            Xs[k][r] = xv.x; Xs[k + 1][r] = xv.y; Xs[k + 2][r] = xv.z; Xs[k + 3][r] = xv.w;
        }
        __syncthreads();
        #pragma unroll 16
        for (int k = 0; k < 64; k++) {
            float a[8], b[8];
            *(float4*)(a)     = *(const float4*)&Xs[k][tr];
            *(float4*)(a + 4) = *(const float4*)&Xs[k][tr + 4];
            *(float4*)(b)     = *(const float4*)&Ws[k][tc];
            *(float4*)(b + 4) = *(const float4*)&Ws[k][tc + 4];
            #pragma unroll
            for (int i = 0; i < 8; i++)
                #pragma unroll
                for (int j = 0; j < 8; j++)
                    acc[i][j] += a[i] * b[j];
        }
        __syncthreads();
    }
    #pragma unroll
    for (int i = 0; i < 8; i++) {
        int r = row0 + tr + i;
        if (r < n) {
            *(float4*)&C[r * 64 + tc]     = make_float4(acc[i][0], acc[i][1], acc[i][2], acc[i][3]);
            *(float4*)&C[r * 64 + tc + 4] = make_float4(acc[i][4], acc[i][5], acc[i][6], acc[i][7]);
        }
    }
}

// =================== per-node attention logits ==============================
__global__ void compute_elr(const float* __restrict__ feat,
                            const float* __restrict__ al, const float* __restrict__ ar,
                            float* __restrict__ el, float* __restrict__ er) {
    int i = blockIdx.x * blockDim.x + threadIdx.x;   // n*4 + h
    if (i >= NN * 4) return;
    int h = i & 3;
    int n = i >> 2;
    const float4* f = (const float4*)(feat + n * 64 + h * 16);
    const float4* a = (const float4*)(al + h * 16);
    const float4* b = (const float4*)(ar + h * 16);
    float s1 = 0.f, s2 = 0.f;
    #pragma unroll
    for (int j = 0; j < 4; j++) {
        float4 fv = f[j], av = __ldg(a + j), bv = __ldg(b + j);
        s1 += fv.x * av.x + fv.y * av.y + fv.z * av.z + fv.w * av.w;
        s2 += fv.x * bv.x + fv.y * bv.y + fv.z * bv.z + fv.w * bv.w;
    }
    el[i] = s1;
    er[i] = s2;
}

// =================== fused single-pass aggregation ==========================
// 16 threads per node; thread j handles feature float4 j (head h = j>>2).
// out_node = (sum_e ee*feat[src]) / (sum_e ee) + res + bias, then activation.

__global__ void __launch_bounds__(256) agg_layer1(
        const int* __restrict__ rowptr, const int* __restrict__ csrc,
        const float* __restrict__ el, const float* __restrict__ er,
        const float* __restrict__ feat, const float* __restrict__ res1,
        const float* __restrict__ b1, float* __restrict__ h1) {
    int gid = blockIdx.x * 256 + threadIdx.x;
    int node = gid >> 4;
    if (node >= NN) return;
    int j = gid & 15;
    int h = j >> 2;
    float ern = __ldg(er + node * 4 + h);
    int beg = __ldg(rowptr + node), end = __ldg(rowptr + node + 1);
    float den = 0.f;
    float4 acc = make_float4(0.f, 0.f, 0.f, 0.f);
    for (int k = beg; k < end; k++) {
        int s = __ldg(csrc + k);
        float e = __ldg(el + s * 4 + h) + ern;
        e = (e > 0.f) ? e : 0.2f * e;
        float ee = __expf(e);
        den += ee;
        float4 f = __ldg((const float4*)(feat + s * 64 + j * 4));
        acc.x += ee * f.x; acc.y += ee * f.y; acc.z += ee * f.z; acc.w += ee * f.w;
    }
    float r = (den > 0.f) ? (1.f / den) : 0.f;
    float4 rs = *(const float4*)(res1 + node * 64 + j * 4);
    float4 bb = __ldg((const float4*)(b1 + j * 4));
    float4 o;
    o.x = acc.x * r + rs.x + bb.x;
    o.y = acc.y * r + rs.y + bb.y;
    o.z = acc.z * r + rs.z + bb.z;
    o.w = acc.w * r + rs.w + bb.w;
    o.x = (o.x > 0.f) ? o.x : expm1f(o.x);
    o.y = (o.y > 0.f) ? o.y : expm1f(o.y);
    o.z = (o.z > 0.f) ? o.z : expm1f(o.z);
    o.w = (o.w > 0.f) ? o.w : expm1f(o.w);
    *(float4*)(h1 + node * 64 + j * 4) = o;
}

__global__ void __launch_bounds__(256) agg_layer2(
        const int* __restrict__ rowptr, const int* __restrict__ csrc,
        const float* __restrict__ el, const float* __restrict__ er,
        const float* __restrict__ feat, const float* __restrict__ h1,
        const float* __restrict__ b2, float* __restrict__ out) {
    int gid = blockIdx.x * 256 + threadIdx.x;
    int node = gid >> 4;
    if (node >= NN) return;
    int j = gid & 15;
    int h = j >> 2;
    float ern = __ldg(er + node * 4 + h);
    int beg = __ldg(rowptr + node), end = __ldg(rowptr + node + 1);
    float den = 0.f;
    float4 acc = make_float4(0.f, 0.f, 0.f, 0.f);
    for (int k = beg; k < end; k++) {
        int s = __ldg(csrc + k);
        float e = __ldg(el + s * 4 + h) + ern;
        e = (e > 0.f) ? e : 0.2f * e;
        float ee = __expf(e);
        den += ee;
        float4 f = __ldg((const float4*)(feat + s * 64 + j * 4));
        acc.x += ee * f.x; acc.y += ee * f.y; acc.z += ee * f.z; acc.w += ee * f.w;
    }
    float r = (den > 0.f) ? (1.f / den) : 0.f;
    float4 rs = *(const float4*)(h1 + node * 64 + j * 4);   // identity residual
    float4 bb = __ldg((const float4*)(b2 + j * 4));
    float4 o;
    o.x = acc.x * r + rs.x + bb.x;
    o.y = acc.y * r + rs.y + bb.y;
    o.z = acc.z * r + rs.z + bb.z;
    o.w = acc.w * r + rs.w + bb.w;
    // mean over heads: threads j, j^4, j^8 hold same dd group across heads
    o.x += __shfl_xor_sync(~0u, o.x, 4); o.x += __shfl_xor_sync(~0u, o.x, 8);
    o.y += __shfl_xor_sync(~0u, o.y, 4); o.y += __shfl_xor_sync(~0u, o.y, 8);
    o.z += __shfl_xor_sync(~0u, o.z, 4); o.z += __shfl_xor_sync(~0u, o.z, 8);
    o.w += __shfl_xor_sync(~0u, o.w, 4); o.w += __shfl_xor_sync(~0u, o.w, 8);
    if (j < 4) {
        float4 m = make_float4(0.25f * o.x, 0.25f * o.y, 0.25f * o.z, 0.25f * o.w);
        *(float4*)(out + node * 16 + j * 4) = m;
    }
}

// =================== launch ==================================================
extern "C" void kernel_launch(void* const* d_in, const int* in_sizes, int n_in,
                              void* d_out, int out_size) {
    const float* x     = (const float*)d_in[0];
    const int*   src   = (const int*)  d_in[1];
    const int*   dst   = (const int*)  d_in[2];
    const float* W1    = (const float*)d_in[3];
    const float* al1   = (const float*)d_in[4];
    const float* ar1   = (const float*)d_in[5];
    const float* resW1 = (const float*)d_in[6];
    const float* b1    = (const float*)d_in[7];
    const float* W2    = (const float*)d_in[8];
    const float* al2   = (const float*)d_in[9];
    const float* ar2   = (const float*)d_in[10];
    const float* b2    = (const float*)d_in[11];
    float* out = (float*)d_out;

    float *feat, *res1, *h1, *el, *er;
    int *cnt, *rowptr, *cursor, *csrc, *bsum, *boff;
    cudaGetSymbolAddress((void**)&feat,   g_feat);
    cudaGetSymbolAddress((void**)&res1,   g_res1);
    cudaGetSymbolAddress((void**)&h1,     g_h1);
    cudaGetSymbolAddress((void**)&el,     g_el);
    cudaGetSymbolAddress((void**)&er,     g_er);
    cudaGetSymbolAddress((void**)&cnt,    g_cnt);
    cudaGetSymbolAddress((void**)&rowptr, g_rowptr);
    cudaGetSymbolAddress((void**)&cursor, g_cursor);
    cudaGetSymbolAddress((void**)&csrc,   g_csrc);
    cudaGetSymbolAddress((void**)&bsum,   g_bsum);
    cudaGetSymbolAddress((void**)&boff,   g_boff);

    const int T = 256;
    const int edgeBlocks = (EE + T - 1) / T;          // 6250
    const int gemmBlocks = (NN + 127) / 128;          // 782
    const int elrBlocks  = (NN * 4 + T - 1) / T;      // 1563
    const int aggBlocks  = (NN * 16 + T - 1) / T;     // 6250

    // ---- CSR build (per-call; depends only on src/dst) ----
    zero_cnt<<<(NN + T - 1) / T, T>>>(cnt);
    hist_dst<<<edgeBlocks, T>>>(dst, cnt);
    block_sums<<<NB, 1024>>>(cnt, bsum);
    scan_bsums<<<1, 128>>>(bsum, boff);
    scan_final<<<NB, 1024>>>(cnt, boff, rowptr, cursor);
    scatter_edges<<<edgeBlocks, T>>>(src, dst, cursor, csrc);

    // ---- layer 1 ----
    gemm128x64<<<gemmBlocks, 128>>>(x, W1,    feat, NN, 128);
    gemm128x64<<<gemmBlocks, 128>>>(x, resW1, res1, NN, 128);
    compute_elr<<<elrBlocks, T>>>(feat, al1, ar1, el, er);
    agg_layer1<<<aggBlocks, T>>>(rowptr, csrc, el, er, feat, res1, b1, h1);

    // ---- layer 2 ----
    gemm128x64<<<gemmBlocks, 128>>>(h1, W2, feat, NN, 64);
    compute_elr<<<elrBlocks, T>>>(feat, al2, ar2, el, er);
    agg_layer2<<<aggBlocks, T>>>(rowptr, csrc, el, er, feat, h1, b2, out);
}

// round 3
// speedup vs baseline: 2.1460x; 1.2322x over previous
#include <cuda_runtime.h>
#include <cuda_bf16.h>
#include <math.h>

#define NN 100000
#define EE 1600000
#define NB 98           // ceil(NN/1024)

// ---------------- scratch (device globals; no allocation allowed) ----------
__device__ __align__(256) float g_feat[NN * 64];
__device__ __align__(256) float g_res1[NN * 64];
__device__ __align__(256) float g_h1  [NN * 64];
__device__ __align__(256) float g_el  [NN * 4];
__device__ __align__(256) float g_er  [NN * 4];
__device__ __align__(256) int   g_cnt [NN];
__device__ __align__(256) int   g_rowptr[NN + 1];
__device__ __align__(256) int   g_cursor[NN];
__device__ __align__(256) int   g_csrc[EE];
__device__ __align__(256) int   g_bsum[NB];
__device__ __align__(256) int   g_boff[NB];

// =================== CSR build ==============================================
__global__ void zero_cnt(int* __restrict__ cnt) {
    int i = blockIdx.x * blockDim.x + threadIdx.x;
    if (i < NN) cnt[i] = 0;
}

__global__ void hist_dst(const int* __restrict__ dst, int* __restrict__ cnt) {
    int e = blockIdx.x * blockDim.x + threadIdx.x;
    if (e < EE) atomicAdd(cnt + dst[e], 1);
}

__global__ void block_sums(const int* __restrict__ cnt, int* __restrict__ bsum) {
    __shared__ int wsum[32];
    int t = threadIdx.x;
    int i = blockIdx.x * 1024 + t;
    int v = (i < NN) ? cnt[i] : 0;
    #pragma unroll
    for (int o = 16; o > 0; o >>= 1) v += __shfl_down_sync(~0u, v, o);
    if ((t & 31) == 0) wsum[t >> 5] = v;
    __syncthreads();
    if (t < 32) {
        int s = wsum[t];
        #pragma unroll
        for (int o = 16; o > 0; o >>= 1) s += __shfl_down_sync(~0u, s, o);
        if (t == 0) bsum[blockIdx.x] = s;
    }
}

__global__ void scan_bsums(const int* __restrict__ bsum, int* __restrict__ boff) {
    __shared__ int buf[128];
    int t = threadIdx.x;
    int v = (t < NB) ? bsum[t] : 0;
    buf[t] = v;
    __syncthreads();
    #pragma unroll
    for (int o = 1; o < 128; o <<= 1) {
        int x = (t >= o) ? buf[t - o] : 0;
        __syncthreads();
        buf[t] += x;
        __syncthreads();
    }
    if (t < NB) boff[t] = buf[t] - v;   // exclusive
}

__global__ void scan_final(const int* __restrict__ cnt, const int* __restrict__ boff,
                           int* __restrict__ rowptr, int* __restrict__ cursor) {
    __shared__ int wsum[32];
    int t = threadIdx.x;
    int i = blockIdx.x * 1024 + t;
    int v = (i < NN) ? cnt[i] : 0;
    int lane = t & 31, wid = t >> 5;
    int x = v;
    #pragma unroll
    for (int o = 1; o < 32; o <<= 1) {
        int y = __shfl_up_sync(~0u, x, o);
        if (lane >= o) x += y;
    }
    if (lane == 31) wsum[wid] = x;
    __syncthreads();
    if (wid == 0) {
        int s = wsum[lane];
        #pragma unroll
        for (int o = 1; o < 32; o <<= 1) {
            int y = __shfl_up_sync(~0u, s, o);
            if (lane >= o) s += y;
        }
        wsum[lane] = s;
    }
    __syncthreads();
    int incl = x + ((wid > 0) ? wsum[wid - 1] : 0) + boff[blockIdx.x];
    if (i < NN) {
        rowptr[i + 1] = incl;
        cursor[i] = incl - v;
    }
    if (i == 0) rowptr[0] = 0;
}

__global__ void scatter_edges(const int* __restrict__ src, const int* __restrict__ dst,
                              int* __restrict__ cursor, int* __restrict__ csrc) {
    int e = blockIdx.x * blockDim.x + threadIdx.x;
    if (e >= EE) return;
    int pos = atomicAdd(cursor + dst[e], 1);
    csrc[pos] = src[e];
}

// =================== tensor-core GEMM (3xTF32) ==============================
// C[n, NCOLS] = X[n, K] @ W[K, NCOLS], fp32 in/out, tf32 hi/lo split.
// Block tile: M=128 x N=NCOLS. Warps: 4 along M (32 rows each) x (NCOLS/64) along N.
// Per warp: 2 m16 tiles x 8 n8 tiles. K chunked by 32 through smem.

__device__ __forceinline__ unsigned f2tf32(float x) {
    unsigned r;
    asm("cvt.rna.tf32.f32 %0, %1;" : "=r"(r) : "f"(x));
    return r;
}

__device__ __forceinline__ void mma_tf32(float* c, const unsigned* a, unsigned b0, unsigned b1) {
    asm volatile(
        "mma.sync.aligned.m16n8k8.row.col.f32.tf32.tf32.f32 "
        "{%0,%1,%2,%3}, {%4,%5,%6,%7}, {%8,%9}, {%0,%1,%2,%3};"
        : "+f"(c[0]), "+f"(c[1]), "+f"(c[2]), "+f"(c[3])
        : "r"(a[0]), "r"(a[1]), "r"(a[2]), "r"(a[3]), "r"(b0), "r"(b1));
}

template<int NCOLS>
__global__ void __launch_bounds__(NCOLS == 128 ? 256 : 128) gemm_tc(
        const float* __restrict__ X, const float* __restrict__ Wa,
        const float* __restrict__ Wb,
        float* __restrict__ Ca, float* __restrict__ Cb,
        int n, int K) {
    constexpr int T    = (NCOLS == 128) ? 256 : 128;
    constexpr int XSTR = 36;                          // 36 % 32 == 4 -> conflict-free A frags
    constexpr int WSTR = (NCOLS == 128) ? 136 : 72;   // % 32 == 8  -> conflict-free B frags
    extern __shared__ unsigned sm[];
    unsigned* Xh = sm;
    unsigned* Xl = Xh + 128 * XSTR;
    unsigned* Wh = Xl + 128 * XSTR;
    unsigned* Wl = Wh + 32 * WSTR;

    const int t = threadIdx.x;
    const int lane = t & 31, wid = t >> 5;
    const int wm = wid & 3, wn = wid >> 2;
    const int g = lane >> 2, tig = lane & 3;
    const int row0 = blockIdx.x * 128;

    float acc[2][8][4] = {};

    for (int k0 = 0; k0 < K; k0 += 32) {
        // ---- load + split X tile: 128 rows x 32 k ----
        #pragma unroll
        for (int idx = t; idx < 1024; idx += T) {
            int r = idx >> 3, c4 = (idx & 7) << 2;
            int row = row0 + r;
            float4 v = (row < n) ? *(const float4*)&X[row * K + k0 + c4]
                                 : make_float4(0.f, 0.f, 0.f, 0.f);
            uint4 h, l;
            h.x = f2tf32(v.x); l.x = f2tf32(v.x - __uint_as_float(h.x));
            h.y = f2tf32(v.y); l.y = f2tf32(v.y - __uint_as_float(h.y));
            h.z = f2tf32(v.z); l.z = f2tf32(v.z - __uint_as_float(h.z));
            h.w = f2tf32(v.w); l.w = f2tf32(v.w - __uint_as_float(h.w));
            *(uint4*)&Xh[r * XSTR + c4] = h;
            *(uint4*)&Xl[r * XSTR + c4] = l;
        }
        // ---- load + split W tile: 32 k x NCOLS ----
        #pragma unroll
        for (int idx = t; idx < 32 * NCOLS / 4; idx += T) {
            int k = idx / (NCOLS / 4);
            int c4 = (idx % (NCOLS / 4)) << 2;
            const float* srcp = (NCOLS == 64 || c4 < 64)
                              ? &Wa[(k0 + k) * 64 + c4]
                              : &Wb[(k0 + k) * 64 + c4 - 64];
            float4 v = *(const float4*)srcp;
            uint4 h, l;
            h.x = f2tf32(v.x); l.x = f2tf32(v.x - __uint_as_float(h.x));
            h.y = f2tf32(v.y); l.y = f2tf32(v.y - __uint_as_float(h.y));
            h.z = f2tf32(v.z); l.z = f2tf32(v.z - __uint_as_float(h.z));
            h.w = f2tf32(v.w); l.w = f2tf32(v.w - __uint_as_float(h.w));
            *(uint4*)&Wh[k * WSTR + c4] = h;
            *(uint4*)&Wl[k * WSTR + c4] = l;
        }
        __syncthreads();

        #pragma unroll
        for (int kk = 0; kk < 4; kk++) {
            unsigned ah[2][4], al_[2][4];
            #pragma unroll
            for (int i = 0; i < 2; i++) {
                int rb = wm * 32 + 16 * i;
                int c0 = kk * 8 + tig;
                ah[i][0] = Xh[(rb + g) * XSTR + c0];
                ah[i][1] = Xh[(rb + g + 8) * XSTR + c0];
                ah[i][2] = Xh[(rb + g) * XSTR + c0 + 4];
                ah[i][3] = Xh[(rb + g + 8) * XSTR + c0 + 4];
                al_[i][0] = Xl[(rb + g) * XSTR + c0];
                al_[i][1] = Xl[(rb + g + 8) * XSTR + c0];
                al_[i][2] = Xl[(rb + g) * XSTR + c0 + 4];
                al_[i][3] = Xl[(rb + g + 8) * XSTR + c0 + 4];
            }
            #pragma unroll
            for (int j = 0; j < 8; j++) {
                int col = wn * 64 + j * 8 + g;
                int kr = kk * 8 + tig;
                unsigned bh0 = Wh[kr * WSTR + col];
                unsigned bh1 = Wh[(kr + 4) * WSTR + col];
                unsigned bl0 = Wl[kr * WSTR + col];
                unsigned bl1 = Wl[(kr + 4) * WSTR + col];
                #pragma unroll
                for (int i = 0; i < 2; i++) {
                    mma_tf32(acc[i][j], ah[i],  bh0, bh1);
                    mma_tf32(acc[i][j], al_[i], bh0, bh1);
                    mma_tf32(acc[i][j], ah[i],  bl0, bl1);
                }
            }
        }
        __syncthreads();
    }

    // ---- epilogue ----
    #pragma unroll
    for (int i = 0; i < 2; i++) {
        #pragma unroll
        for (int j = 0; j < 8; j++) {
            int row = row0 + wm * 32 + 16 * i + g;
            int col = wn * 64 + j * 8 + 2 * tig;
            float* outp;
            int c = col;
            if (NCOLS == 128 && col >= 64) { outp = Cb; c = col - 64; }
            else                           { outp = Ca; }
            if (row < n)
                *(float2*)&outp[row * 64 + c] = make_float2(acc[i][j][0], acc[i][j][1]);
            if (row + 8 < n)
                *(float2*)&outp[(row + 8) * 64 + c] = make_float2(acc[i][j][2], acc[i][j][3]);
        }
    }
}

// =================== per-node attention logits ==============================
__global__ void compute_elr(const float* __restrict__ feat,
                            const float* __restrict__ al, const float* __restrict__ ar,
                            float* __restrict__ el, float* __restrict__ er) {
    int i = blockIdx.x * blockDim.x + threadIdx.x;   // n*4 + h
    if (i >= NN * 4) return;
    int h = i & 3;
    int n = i >> 2;
    const float4* f = (const float4*)(feat + n * 64 + h * 16);
    const float4* a = (const float4*)(al + h * 16);
    const float4* b = (const float4*)(ar + h * 16);
    float s1 = 0.f, s2 = 0.f;
    #pragma unroll
    for (int j = 0; j < 4; j++) {
        float4 fv = f[j], av = __ldg(a + j), bv = __ldg(b + j);
        s1 += fv.x * av.x + fv.y * av.y + fv.z * av.z + fv.w * av.w;
        s2 += fv.x * bv.x + fv.y * bv.y + fv.z * bv.z + fv.w * bv.w;
    }
    el[i] = s1;
    er[i] = s2;
}

// =================== fused single-pass aggregation ==========================
__global__ void __launch_bounds__(256) agg_layer1(
        const int* __restrict__ rowptr, const int* __restrict__ csrc,
        const float* __restrict__ el, const float* __restrict__ er,
        const float* __restrict__ feat, const float* __restrict__ res1,
        const float* __restrict__ b1, float* __restrict__ h1) {
    int gid = blockIdx.x * 256 + threadIdx.x;
    int node = gid >> 4;
    if (node >= NN) return;
    int j = gid & 15;
    int h = j >> 2;
    float ern = __ldg(er + node * 4 + h);
    int beg = __ldg(rowptr + node), end = __ldg(rowptr + node + 1);
    float den = 0.f;
    float4 acc = make_float4(0.f, 0.f, 0.f, 0.f);
    for (int k = beg; k < end; k++) {
        int s = __ldg(csrc + k);
        float e = __ldg(el + s * 4 + h) + ern;
        e = (e > 0.f) ? e : 0.2f * e;
        float ee = __expf(e);
        den += ee;
        float4 f = __ldg((const float4*)(feat + s * 64 + j * 4));
        acc.x += ee * f.x; acc.y += ee * f.y; acc.z += ee * f.z; acc.w += ee * f.w;
    }
    float r = (den > 0.f) ? (1.f / den) : 0.f;
    float4 rs = *(const float4*)(res1 + node * 64 + j * 4);
    float4 bb = __ldg((const float4*)(b1 + j * 4));
    float4 o;
    o.x = acc.x * r + rs.x + bb.x;
    o.y = acc.y * r + rs.y + bb.y;
    o.z = acc.z * r + rs.z + bb.z;
    o.w = acc.w * r + rs.w + bb.w;
    o.x = (o.x > 0.f) ? o.x : expm1f(o.x);
    o.y = (o.y > 0.f) ? o.y : expm1f(o.y);
    o.z = (o.z > 0.f) ? o.z : expm1f(o.z);
    o.w = (o.w > 0.f) ? o.w : expm1f(o.w);
    *(float4*)(h1 + node * 64 + j * 4) = o;
}

__global__ void __launch_bounds__(256) agg_layer2(
        const int* __restrict__ rowptr, const int* __restrict__ csrc,
        const float* __restrict__ el, const float* __restrict__ er,
        const float* __restrict__ feat, const float* __restrict__ h1,
        const float* __restrict__ b2, float* __restrict__ out) {
    int gid = blockIdx.x * 256 + threadIdx.x;
    int node = gid >> 4;
    if (node >= NN) return;
    int j = gid & 15;
    int h = j >> 2;
    float ern = __ldg(er + node * 4 + h);
    int beg = __ldg(rowptr + node), end = __ldg(rowptr + node + 1);
    float den = 0.f;
    float4 acc = make_float4(0.f, 0.f, 0.f, 0.f);
    for (int k = beg; k < end; k++) {
        int s = __ldg(csrc + k);
        float e = __ldg(el + s * 4 + h) + ern;
        e = (e > 0.f) ? e : 0.2f * e;
        float ee = __expf(e);
        den += ee;
        float4 f = __ldg((const float4*)(feat + s * 64 + j * 4));
        acc.x += ee * f.x; acc.y += ee * f.y; acc.z += ee * f.z; acc.w += ee * f.w;
    }
    float r = (den > 0.f) ? (1.f / den) : 0.f;
    float4 rs = *(const float4*)(h1 + node * 64 + j * 4);   // identity residual
    float4 bb = __ldg((const float4*)(b2 + j * 4));
    float4 o;
    o.x = acc.x * r + rs.x + bb.x;
    o.y = acc.y * r + rs.y + bb.y;
    o.z = acc.z * r + rs.z + bb.z;
    o.w = acc.w * r + rs.w + bb.w;
    o.x += __shfl_xor_sync(~0u, o.x, 4); o.x += __shfl_xor_sync(~0u, o.x, 8);
    o.y += __shfl_xor_sync(~0u, o.y, 4); o.y += __shfl_xor_sync(~0u, o.y, 8);
    o.z += __shfl_xor_sync(~0u, o.z, 4); o.z += __shfl_xor_sync(~0u, o.z, 8);
    o.w += __shfl_xor_sync(~0u, o.w, 4); o.w += __shfl_xor_sync(~0u, o.w, 8);
    if (j < 4) {
        float4 m = make_float4(0.25f * o.x, 0.25f * o.y, 0.25f * o.z, 0.25f * o.w);
        *(float4*)(out + node * 16 + j * 4) = m;
    }
}

// =================== launch ==================================================
extern "C" void kernel_launch(void* const* d_in, const int* in_sizes, int n_in,
                              void* d_out, int out_size) {
    const float* x     = (const float*)d_in[0];
    const int*   src   = (const int*)  d_in[1];
    const int*   dst   = (const int*)  d_in[2];
    const float* W1    = (const float*)d_in[3];
    const float* al1   = (const float*)d_in[4];
    const float* ar1   = (const float*)d_in[5];
    const float* resW1 = (const float*)d_in[6];
    const float* b1    = (const float*)d_in[7];
    const float* W2    = (const float*)d_in[8];
    const float* al2   = (const float*)d_in[9];
    const float* ar2   = (const float*)d_in[10];
    const float* b2    = (const float*)d_in[11];
    float* out = (float*)d_out;

    float *feat, *res1, *h1, *el, *er;
    int *cnt, *rowptr, *cursor, *csrc, *bsum, *boff;
    cudaGetSymbolAddress((void**)&feat,   g_feat);
    cudaGetSymbolAddress((void**)&res1,   g_res1);
    cudaGetSymbolAddress((void**)&h1,     g_h1);
    cudaGetSymbolAddress((void**)&el,     g_el);
    cudaGetSymbolAddress((void**)&er,     g_er);
    cudaGetSymbolAddress((void**)&cnt,    g_cnt);
    cudaGetSymbolAddress((void**)&rowptr, g_rowptr);
    cudaGetSymbolAddress((void**)&cursor, g_cursor);
    cudaGetSymbolAddress((void**)&csrc,   g_csrc);
    cudaGetSymbolAddress((void**)&bsum,   g_bsum);
    cudaGetSymbolAddress((void**)&boff,   g_boff);

    const int T = 256;
    const int edgeBlocks = (EE + T - 1) / T;          // 6250
    const int gemmBlocks = (NN + 127) / 128;          // 782
    const int elrBlocks  = (NN * 4 + T - 1) / T;      // 1563
    const int aggBlocks  = (NN * 16 + T - 1) / T;     // 6250

    const int smem128 = (2 * 128 * 36 + 2 * 32 * 136) * 4;   // 71680
    const int smem64  = (2 * 128 * 36 + 2 * 32 * 72) * 4;    // 55296
    cudaFuncSetAttribute(gemm_tc<128>, cudaFuncAttributeMaxDynamicSharedMemorySize, smem128);
    cudaFuncSetAttribute(gemm_tc<64>,  cudaFuncAttributeMaxDynamicSharedMemorySize, smem64);

    // ---- CSR build ----
    zero_cnt<<<(NN + T - 1) / T, T>>>(cnt);
    hist_dst<<<edgeBlocks, T>>>(dst, cnt);
    block_sums<<<NB, 1024>>>(cnt, bsum);
    scan_bsums<<<1, 128>>>(bsum, boff);
    scan_final<<<NB, 1024>>>(cnt, boff, rowptr, cursor);
    scatter_edges<<<edgeBlocks, T>>>(src, dst, cursor, csrc);

    // ---- layer 1 (fused W1|resW1 GEMM) ----
    gemm_tc<128><<<gemmBlocks, 256, smem128>>>(x, W1, resW1, feat, res1, NN, 128);
    compute_elr<<<elrBlocks, T>>>(feat, al1, ar1, el, er);
    agg_layer1<<<aggBlocks, T>>>(rowptr, csrc, el, er, feat, res1, b1, h1);

    // ---- layer 2 ----
    gemm_tc<64><<<gemmBlocks, 128, smem64>>>(h1, W2, nullptr, feat, nullptr, NN, 64);
    compute_elr<<<elrBlocks, T>>>(feat, al2, ar2, el, er);
    agg_layer2<<<aggBlocks, T>>>(rowptr, csrc, el, er, feat, h1, b2, out);
}

// round 4
// speedup vs baseline: 2.2525x; 1.0496x over previous
#include <cuda_runtime.h>
#include <cuda_fp16.h>
#include <math.h>

#define NN 100000
#define EE 1600000
#define NB 98           // ceil(NN/1024)

// ---------------- scratch (device globals; no allocation allowed) ----------
__device__ __align__(256) float  g_feat [NN * 64];
__device__ __align__(256) __half g_feath[NN * 64];
__device__ __align__(256) float  g_res1 [NN * 64];
__device__ __align__(256) float  g_h1   [NN * 64];
__device__ __align__(256) float  g_el   [NN * 4];
__device__ __align__(256) float  g_er   [NN * 4];
__device__ __align__(256) int    g_cnt  [NN];
__device__ __align__(256) int    g_rowptr[NN + 1];
__device__ __align__(256) int    g_cursor[NN];
__device__ __align__(256) int    g_csrc[EE];
__device__ __align__(256) int    g_bsum[NB];
__device__ __align__(256) int    g_boff[NB];

// =================== CSR build ==============================================
__global__ void zero_cnt(int* __restrict__ cnt) {
    int i = blockIdx.x * blockDim.x + threadIdx.x;
    if (i < NN) cnt[i] = 0;
}

__global__ void hist_dst(const int* __restrict__ dst, int* __restrict__ cnt) {
    int e = blockIdx.x * blockDim.x + threadIdx.x;
    if (e < EE) atomicAdd(cnt + dst[e], 1);
}

__global__ void block_sums(const int* __restrict__ cnt, int* __restrict__ bsum) {
    __shared__ int wsum[32];
    int t = threadIdx.x;
    int i = blockIdx.x * 1024 + t;
    int v = (i < NN) ? cnt[i] : 0;
    #pragma unroll
    for (int o = 16; o > 0; o >>= 1) v += __shfl_down_sync(~0u, v, o);
    if ((t & 31) == 0) wsum[t >> 5] = v;
    __syncthreads();
    if (t < 32) {
        int s = wsum[t];
        #pragma unroll
        for (int o = 16; o > 0; o >>= 1) s += __shfl_down_sync(~0u, s, o);
        if (t == 0) bsum[blockIdx.x] = s;
    }
}

__global__ void scan_bsums(const int* __restrict__ bsum, int* __restrict__ boff) {
    __shared__ int buf[128];
    int t = threadIdx.x;
    int v = (t < NB) ? bsum[t] : 0;
    buf[t] = v;
    __syncthreads();
    #pragma unroll
    for (int o = 1; o < 128; o <<= 1) {
        int x = (t >= o) ? buf[t - o] : 0;
        __syncthreads();
        buf[t] += x;
        __syncthreads();
    }
    if (t < NB) boff[t] = buf[t] - v;   // exclusive
}

__global__ void scan_final(const int* __restrict__ cnt, const int* __restrict__ boff,
                           int* __restrict__ rowptr, int* __restrict__ cursor) {
    __shared__ int wsum[32];
    int t = threadIdx.x;
    int i = blockIdx.x * 1024 + t;
    int v = (i < NN) ? cnt[i] : 0;
    int lane = t & 31, wid = t >> 5;
    int x = v;
    #pragma unroll
    for (int o = 1; o < 32; o <<= 1) {
        int y = __shfl_up_sync(~0u, x, o);
        if (lane >= o) x += y;
    }
    if (lane == 31) wsum[wid] = x;
    __syncthreads();
    if (wid == 0) {
        int s = wsum[lane];
        #pragma unroll
        for (int o = 1; o < 32; o <<= 1) {
            int y = __shfl_up_sync(~0u, s, o);
            if (lane >= o) s += y;
        }
        wsum[lane] = s;
    }
    __syncthreads();
    int incl = x + ((wid > 0) ? wsum[wid - 1] : 0) + boff[blockIdx.x];
    if (i < NN) {
        rowptr[i + 1] = incl;
        cursor[i] = incl - v;
    }
    if (i == 0) rowptr[0] = 0;
}

__global__ void scatter_edges(const int* __restrict__ src, const int* __restrict__ dst,
                              int* __restrict__ cursor, int* __restrict__ csrc) {
    int e = blockIdx.x * blockDim.x + threadIdx.x;
    if (e >= EE) return;
    int pos = atomicAdd(cursor + dst[e], 1);
    csrc[pos] = src[e];
}

// =================== tensor-core GEMM (3xTF32) ==============================
__device__ __forceinline__ unsigned f2tf32(float x) {
    unsigned r;
    asm("cvt.rna.tf32.f32 %0, %1;" : "=r"(r) : "f"(x));
    return r;
}

__device__ __forceinline__ void mma_tf32(float* c, const unsigned* a, unsigned b0, unsigned b1) {
    asm volatile(
        "mma.sync.aligned.m16n8k8.row.col.f32.tf32.tf32.f32 "
        "{%0,%1,%2,%3}, {%4,%5,%6,%7}, {%8,%9}, {%0,%1,%2,%3};"
        : "+f"(c[0]), "+f"(c[1]), "+f"(c[2]), "+f"(c[3])
        : "r"(a[0]), "r"(a[1]), "r"(a[2]), "r"(a[3]), "r"(b0), "r"(b1));
}

// C[n, NCOLS] = X[n, K] @ [Wa|Wb]; Ca also mirrored to fp16 Ch.
template<int NCOLS>
__global__ void __launch_bounds__(NCOLS == 128 ? 256 : 128) gemm_tc(
        const float* __restrict__ X, const float* __restrict__ Wa,
        const float* __restrict__ Wb,
        float* __restrict__ Ca, float* __restrict__ Cb,
        __half* __restrict__ Ch,
        int n, int K) {
    constexpr int T    = (NCOLS == 128) ? 256 : 128;
    constexpr int XSTR = 36;
    constexpr int WSTR = (NCOLS == 128) ? 136 : 72;
    extern __shared__ unsigned sm[];
    unsigned* Xh = sm;
    unsigned* Xl = Xh + 128 * XSTR;
    unsigned* Wh = Xl + 128 * XSTR;
    unsigned* Wl = Wh + 32 * WSTR;

    const int t = threadIdx.x;
    const int lane = t & 31, wid = t >> 5;
    const int wm = wid & 3, wn = wid >> 2;
    const int g = lane >> 2, tig = lane & 3;
    const int row0 = blockIdx.x * 128;

    float acc[2][8][4] = {};

    for (int k0 = 0; k0 < K; k0 += 32) {
        #pragma unroll
        for (int idx = t; idx < 1024; idx += T) {
            int r = idx >> 3, c4 = (idx & 7) << 2;
            int row = row0 + r;
            float4 v = (row < n) ? *(const float4*)&X[row * K + k0 + c4]
                                 : make_float4(0.f, 0.f, 0.f, 0.f);
            uint4 h, l;
            h.x = f2tf32(v.x); l.x = f2tf32(v.x - __uint_as_float(h.x));
            h.y = f2tf32(v.y); l.y = f2tf32(v.y - __uint_as_float(h.y));
            h.z = f2tf32(v.z); l.z = f2tf32(v.z - __uint_as_float(h.z));
            h.w = f2tf32(v.w); l.w = f2tf32(v.w - __uint_as_float(h.w));
            *(uint4*)&Xh[r * XSTR + c4] = h;
            *(uint4*)&Xl[r * XSTR + c4] = l;
        }
        #pragma unroll
        for (int idx = t; idx < 32 * NCOLS / 4; idx += T) {
            int k = idx / (NCOLS / 4);
            int c4 = (idx % (NCOLS / 4)) << 2;
            const float* srcp = (NCOLS == 64 || c4 < 64)
                              ? &Wa[(k0 + k) * 64 + c4]
                              : &Wb[(k0 + k) * 64 + c4 - 64];
            float4 v = *(const float4*)srcp;
            uint4 h, l;
            h.x = f2tf32(v.x); l.x = f2tf32(v.x - __uint_as_float(h.x));
            h.y = f2tf32(v.y); l.y = f2tf32(v.y - __uint_as_float(h.y));
            h.z = f2tf32(v.z); l.z = f2tf32(v.z - __uint_as_float(h.z));
            h.w = f2tf32(v.w); l.w = f2tf32(v.w - __uint_as_float(h.w));
            *(uint4*)&Wh[k * WSTR + c4] = h;
            *(uint4*)&Wl[k * WSTR + c4] = l;
        }
        __syncthreads();

        #pragma unroll
        for (int kk = 0; kk < 4; kk++) {
            unsigned ah[2][4], al_[2][4];
            #pragma unroll
            for (int i = 0; i < 2; i++) {
                int rb = wm * 32 + 16 * i;
                int c0 = kk * 8 + tig;
                ah[i][0] = Xh[(rb + g) * XSTR + c0];
                ah[i][1] = Xh[(rb + g + 8) * XSTR + c0];
                ah[i][2] = Xh[(rb + g) * XSTR + c0 + 4];
                ah[i][3] = Xh[(rb + g + 8) * XSTR + c0 + 4];
                al_[i][0] = Xl[(rb + g) * XSTR + c0];
                al_[i][1] = Xl[(rb + g + 8) * XSTR + c0];
                al_[i][2] = Xl[(rb + g) * XSTR + c0 + 4];
                al_[i][3] = Xl[(rb + g + 8) * XSTR + c0 + 4];
            }
            #pragma unroll
            for (int j = 0; j < 8; j++) {
                int col = wn * 64 + j * 8 + g;
                int kr = kk * 8 + tig;
                unsigned bh0 = Wh[kr * WSTR + col];
                unsigned bh1 = Wh[(kr + 4) * WSTR + col];
                unsigned bl0 = Wl[kr * WSTR + col];
                unsigned bl1 = Wl[(kr + 4) * WSTR + col];
                #pragma unroll
                for (int i = 0; i < 2; i++) {
                    mma_tf32(acc[i][j], ah[i],  bh0, bh1);
                    mma_tf32(acc[i][j], al_[i], bh0, bh1);
                    mma_tf32(acc[i][j], ah[i],  bl0, bl1);
                }
            }
        }
        __syncthreads();
    }

    #pragma unroll
    for (int i = 0; i < 2; i++) {
        #pragma unroll
        for (int j = 0; j < 8; j++) {
            int row = row0 + wm * 32 + 16 * i + g;
            int col = wn * 64 + j * 8 + 2 * tig;
            bool toB = (NCOLS == 128 && col >= 64);
            float* outp = toB ? Cb : Ca;
            int c = toB ? col - 64 : col;
            if (row < n) {
                *(float2*)&outp[row * 64 + c] = make_float2(acc[i][j][0], acc[i][j][1]);
                if (!toB) *(__half2*)&Ch[row * 64 + c] = __floats2half2_rn(acc[i][j][0], acc[i][j][1]);
            }
            if (row + 8 < n) {
                *(float2*)&outp[(row + 8) * 64 + c] = make_float2(acc[i][j][2], acc[i][j][3]);
                if (!toB) *(__half2*)&Ch[(row + 8) * 64 + c] = __floats2half2_rn(acc[i][j][2], acc[i][j][3]);
            }
        }
    }
}

// =================== per-node attention logits ==============================
__global__ void compute_elr(const float* __restrict__ feat,
                            const float* __restrict__ al, const float* __restrict__ ar,
                            float* __restrict__ el, float* __restrict__ er) {
    int i = blockIdx.x * blockDim.x + threadIdx.x;   // n*4 + h
    if (i >= NN * 4) return;
    int h = i & 3;
    int n = i >> 2;
    const float4* f = (const float4*)(feat + n * 64 + h * 16);
    const float4* a = (const float4*)(al + h * 16);
    const float4* b = (const float4*)(ar + h * 16);
    float s1 = 0.f, s2 = 0.f;
    #pragma unroll
    for (int j = 0; j < 4; j++) {
        float4 fv = f[j], av = __ldg(a + j), bv = __ldg(b + j);
        s1 += fv.x * av.x + fv.y * av.y + fv.z * av.z + fv.w * av.w;
        s2 += fv.x * bv.x + fv.y * bv.y + fv.z * bv.z + fv.w * bv.w;
    }
    el[i] = s1;
    er[i] = s2;
}

// =================== fused single-pass aggregation (fp16 gather) ============
__global__ void __launch_bounds__(256) agg_layer1(
        const int* __restrict__ rowptr, const int* __restrict__ csrc,
        const float* __restrict__ el, const float* __restrict__ er,
        const __half* __restrict__ feath, const float* __restrict__ res1,
        const float* __restrict__ b1, float* __restrict__ h1) {
    int gid = blockIdx.x * 256 + threadIdx.x;
    int node = gid >> 4;
    if (node >= NN) return;
    int j = gid & 15;
    int h = j >> 2;
    float ern = __ldg(er + node * 4 + h);
    int beg = __ldg(rowptr + node), end = __ldg(rowptr + node + 1);
    float den = 0.f;
    float4 acc = make_float4(0.f, 0.f, 0.f, 0.f);
    for (int k = beg; k < end; k++) {
        int s = __ldg(csrc + k);
        float e = __ldg(el + s * 4 + h) + ern;
        e = (e > 0.f) ? e : 0.2f * e;
        float ee = __expf(e);
        den += ee;
        uint2 raw = __ldg((const uint2*)(feath + s * 64 + j * 4));
        float2 f01 = __half22float2(*(const __half2*)&raw.x);
        float2 f23 = __half22float2(*(const __half2*)&raw.y);
        acc.x += ee * f01.x; acc.y += ee * f01.y; acc.z += ee * f23.x; acc.w += ee * f23.y;
    }
    float r = (den > 0.f) ? (1.f / den) : 0.f;
    float4 rs = *(const float4*)(res1 + node * 64 + j * 4);
    float4 bb = __ldg((const float4*)(b1 + j * 4));
    float4 o;
    o.x = acc.x * r + rs.x + bb.x;
    o.y = acc.y * r + rs.y + bb.y;
    o.z = acc.z * r + rs.z + bb.z;
    o.w = acc.w * r + rs.w + bb.w;
    o.x = (o.x > 0.f) ? o.x : expm1f(o.x);
    o.y = (o.y > 0.f) ? o.y : expm1f(o.y);
    o.z = (o.z > 0.f) ? o.z : expm1f(o.z);
    o.w = (o.w > 0.f) ? o.w : expm1f(o.w);
    *(float4*)(h1 + node * 64 + j * 4) = o;
}

__global__ void __launch_bounds__(256) agg_layer2(
        const int* __restrict__ rowptr, const int* __restrict__ csrc,
        const float* __restrict__ el, const float* __restrict__ er,
        const __half* __restrict__ feath, const float* __restrict__ h1,
        const float* __restrict__ b2, float* __restrict__ out) {
    int gid = blockIdx.x * 256 + threadIdx.x;
    int node = gid >> 4;
    if (node >= NN) return;
    int j = gid & 15;
    int h = j >> 2;
    float ern = __ldg(er + node * 4 + h);
    int beg = __ldg(rowptr + node), end = __ldg(rowptr + node + 1);
    float den = 0.f;
    float4 acc = make_float4(0.f, 0.f, 0.f, 0.f);
    for (int k = beg; k < end; k++) {
        int s = __ldg(csrc + k);
        float e = __ldg(el + s * 4 + h) + ern;
        e = (e > 0.f) ? e : 0.2f * e;
        float ee = __expf(e);
        den += ee;
        uint2 raw = __ldg((const uint2*)(feath + s * 64 + j * 4));
        float2 f01 = __half22float2(*(const __half2*)&raw.x);
        float2 f23 = __half22float2(*(const __half2*)&raw.y);
        acc.x += ee * f01.x; acc.y += ee * f01.y; acc.z += ee * f23.x; acc.w += ee * f23.y;
    }
    float r = (den > 0.f) ? (1.f / den) : 0.f;
    float4 rs = *(const float4*)(h1 + node * 64 + j * 4);   // identity residual
    float4 bb = __ldg((const float4*)(b2 + j * 4));
    float4 o;
    o.x = acc.x * r + rs.x + bb.x;
    o.y = acc.y * r + rs.y + bb.y;
    o.z = acc.z * r + rs.z + bb.z;
    o.w = acc.w * r + rs.w + bb.w;
    o.x += __shfl_xor_sync(~0u, o.x, 4); o.x += __shfl_xor_sync(~0u, o.x, 8);
    o.y += __shfl_xor_sync(~0u, o.y, 4); o.y += __shfl_xor_sync(~0u, o.y, 8);
    o.z += __shfl_xor_sync(~0u, o.z, 4); o.z += __shfl_xor_sync(~0u, o.z, 8);
    o.w += __shfl_xor_sync(~0u, o.w, 4); o.w += __shfl_xor_sync(~0u, o.w, 8);
    if (j < 4) {
        float4 m = make_float4(0.25f * o.x, 0.25f * o.y, 0.25f * o.z, 0.25f * o.w);
        *(float4*)(out + node * 16 + j * 4) = m;
    }
}

// =================== launch ==================================================
extern "C" void kernel_launch(void* const* d_in, const int* in_sizes, int n_in,
                              void* d_out, int out_size) {
    const float* x     = (const float*)d_in[0];
    const int*   src   = (const int*)  d_in[1];
    const int*   dst   = (const int*)  d_in[2];
    const float* W1    = (const float*)d_in[3];
    const float* al1   = (const float*)d_in[4];
    const float* ar1   = (const float*)d_in[5];
    const float* resW1 = (const float*)d_in[6];
    const float* b1    = (const float*)d_in[7];
    const float* W2    = (const float*)d_in[8];
    const float* al2   = (const float*)d_in[9];
    const float* ar2   = (const float*)d_in[10];
    const float* b2    = (const float*)d_in[11];
    float* out = (float*)d_out;

    float *feat, *res1, *h1, *el, *er;
    __half* feath;
    int *cnt, *rowptr, *cursor, *csrc, *bsum, *boff;
    cudaGetSymbolAddress((void**)&feat,   g_feat);
    cudaGetSymbolAddress((void**)&feath,  g_feath);
    cudaGetSymbolAddress((void**)&res1,   g_res1);
    cudaGetSymbolAddress((void**)&h1,     g_h1);
    cudaGetSymbolAddress((void**)&el,     g_el);
    cudaGetSymbolAddress((void**)&er,     g_er);
    cudaGetSymbolAddress((void**)&cnt,    g_cnt);
    cudaGetSymbolAddress((void**)&rowptr, g_rowptr);
    cudaGetSymbolAddress((void**)&cursor, g_cursor);
    cudaGetSymbolAddress((void**)&csrc,   g_csrc);
    cudaGetSymbolAddress((void**)&bsum,   g_bsum);
    cudaGetSymbolAddress((void**)&boff,   g_boff);

    // second stream + fork/join events (created once, outside any capture;
    // the first harness call is the non-captured correctness run)
    static cudaStream_t s2 = nullptr;
    static cudaEvent_t evFork = nullptr, evJoin = nullptr;
    if (s2 == nullptr) {
        cudaStreamCreateWithFlags(&s2, cudaStreamNonBlocking);
        cudaEventCreateWithFlags(&evFork, cudaEventDisableTiming);
        cudaEventCreateWithFlags(&evJoin, cudaEventDisableTiming);
    }

    const int T = 256;
    const int edgeBlocks = (EE + T - 1) / T;
    const int gemmBlocks = (NN + 127) / 128;
    const int elrBlocks  = (NN * 4 + T - 1) / T;
    const int aggBlocks  = (NN * 16 + T - 1) / T;

    const int smem128 = (2 * 128 * 36 + 2 * 32 * 136) * 4;
    const int smem64  = (2 * 128 * 36 + 2 * 32 * 72) * 4;
    cudaFuncSetAttribute(gemm_tc<128>, cudaFuncAttributeMaxDynamicSharedMemorySize, smem128);
    cudaFuncSetAttribute(gemm_tc<64>,  cudaFuncAttributeMaxDynamicSharedMemorySize, smem64);

    // ---- fork: CSR build on s2, GEMM+elr on main stream ----
    cudaEventRecord(evFork, 0);
    cudaStreamWaitEvent(s2, evFork, 0);

    zero_cnt<<<(NN + T - 1) / T, T, 0, s2>>>(cnt);
    hist_dst<<<edgeBlocks, T, 0, s2>>>(dst, cnt);
    block_sums<<<NB, 1024, 0, s2>>>(cnt, bsum);
    scan_bsums<<<1, 128, 0, s2>>>(bsum, boff);
    scan_final<<<NB, 1024, 0, s2>>>(cnt, boff, rowptr, cursor);
    scatter_edges<<<edgeBlocks, T, 0, s2>>>(src, dst, cursor, csrc);
    cudaEventRecord(evJoin, s2);

    gemm_tc<128><<<gemmBlocks, 256, smem128>>>(x, W1, resW1, feat, res1, feath, NN, 128);
    compute_elr<<<elrBlocks, T>>>(feat, al1, ar1, el, er);

    // ---- join ----
    cudaStreamWaitEvent(0, evJoin, 0);

    agg_layer1<<<aggBlocks, T>>>(rowptr, csrc, el, er, feath, res1, b1, h1);

    // ---- layer 2 ----
    gemm_tc<64><<<gemmBlocks, 128, smem64>>>(h1, W2, nullptr, feat, nullptr, feath, NN, 64);
    compute_elr<<<elrBlocks, T>>>(feat, al2, ar2, el, er);
    agg_layer2<<<aggBlocks, T>>>(rowptr, csrc, el, er, feath, h1, b2, out);
}

// round 5
// speedup vs baseline: 2.4877x; 1.1044x over previous
#include <cuda_runtime.h>
#include <cuda_fp16.h>
#include <math.h>

#define NN 100000
#define EE 1600000

// ---------------- scratch (device globals; no allocation allowed) ----------
__device__ __align__(256) float  g_feat [NN * 64];
__device__ __align__(256) __half g_feath[NN * 64];
__device__ __align__(256) float  g_res1 [NN * 64];
__device__ __align__(256) float  g_h1   [NN * 64];
__device__ __align__(256) float  g_el   [NN * 4];
__device__ __align__(256) float  g_er   [NN * 4];
__device__ __align__(256) int    g_cnt  [NN];
__device__ __align__(256) int    g_start[NN];
__device__ __align__(256) int    g_cursor[NN];
__device__ __align__(256) int    g_csrc[EE];
__device__ int g_total;

// =================== CSR build (unordered segments, no scan) ================
__global__ void zero_cnt(int* __restrict__ cnt, int* __restrict__ total) {
    int i = blockIdx.x * blockDim.x + threadIdx.x;
    if (i < NN) cnt[i] = 0;
    if (i == 0) *total = 0;
}

__global__ void hist_dst(const int* __restrict__ dst, int* __restrict__ cnt) {
    int e = blockIdx.x * blockDim.x + threadIdx.x;
    if (e < EE) atomicAdd(cnt + dst[e], 1);
}

// allocate a contiguous segment per node (any order is fine)
__global__ void alloc_seg(const int* __restrict__ cnt, int* __restrict__ start,
                          int* __restrict__ cursor, int* __restrict__ total) {
    int i = blockIdx.x * blockDim.x + threadIdx.x;
    if (i >= NN) return;
    int c = cnt[i];
    int s = (c > 0) ? atomicAdd(total, c) : 0;
    start[i] = s;
    cursor[i] = s;
}

__global__ void scatter_edges(const int* __restrict__ src, const int* __restrict__ dst,
                              int* __restrict__ cursor, int* __restrict__ csrc) {
    int e = blockIdx.x * blockDim.x + threadIdx.x;
    if (e >= EE) return;
    int pos = atomicAdd(cursor + dst[e], 1);
    csrc[pos] = src[e];
}

// =================== tensor-core GEMM (3xTF32) ==============================
__device__ __forceinline__ unsigned f2tf32(float x) {
    unsigned r;
    asm("cvt.rna.tf32.f32 %0, %1;" : "=r"(r) : "f"(x));
    return r;
}

__device__ __forceinline__ void mma_tf32(float* c, const unsigned* a, unsigned b0, unsigned b1) {
    asm volatile(
        "mma.sync.aligned.m16n8k8.row.col.f32.tf32.tf32.f32 "
        "{%0,%1,%2,%3}, {%4,%5,%6,%7}, {%8,%9}, {%0,%1,%2,%3};"
        : "+f"(c[0]), "+f"(c[1]), "+f"(c[2]), "+f"(c[3])
        : "r"(a[0]), "r"(a[1]), "r"(a[2]), "r"(a[3]), "r"(b0), "r"(b1));
}

template<int NCOLS>
__global__ void __launch_bounds__(NCOLS == 128 ? 256 : 128) gemm_tc(
        const float* __restrict__ X, const float* __restrict__ Wa,
        const float* __restrict__ Wb,
        float* __restrict__ Ca, float* __restrict__ Cb,
        __half* __restrict__ Ch,
        int n, int K) {
    constexpr int T    = (NCOLS == 128) ? 256 : 128;
    constexpr int XSTR = 36;
    constexpr int WSTR = (NCOLS == 128) ? 136 : 72;
    extern __shared__ unsigned sm[];
    unsigned* Xh = sm;
    unsigned* Xl = Xh + 128 * XSTR;
    unsigned* Wh = Xl + 128 * XSTR;
    unsigned* Wl = Wh + 32 * WSTR;

    const int t = threadIdx.x;
    const int lane = t & 31, wid = t >> 5;
    const int wm = wid & 3, wn = wid >> 2;
    const int g = lane >> 2, tig = lane & 3;
    const int row0 = blockIdx.x * 128;

    float acc[2][8][4] = {};

    for (int k0 = 0; k0 < K; k0 += 32) {
        #pragma unroll
        for (int idx = t; idx < 1024; idx += T) {
            int r = idx >> 3, c4 = (idx & 7) << 2;
            int row = row0 + r;
            float4 v = (row < n) ? *(const float4*)&X[row * K + k0 + c4]
                                 : make_float4(0.f, 0.f, 0.f, 0.f);
            uint4 h, l;
            h.x = f2tf32(v.x); l.x = f2tf32(v.x - __uint_as_float(h.x));
            h.y = f2tf32(v.y); l.y = f2tf32(v.y - __uint_as_float(h.y));
            h.z = f2tf32(v.z); l.z = f2tf32(v.z - __uint_as_float(h.z));
            h.w = f2tf32(v.w); l.w = f2tf32(v.w - __uint_as_float(h.w));
            *(uint4*)&Xh[r * XSTR + c4] = h;
            *(uint4*)&Xl[r * XSTR + c4] = l;
        }
        #pragma unroll
        for (int idx = t; idx < 32 * NCOLS / 4; idx += T) {
            int k = idx / (NCOLS / 4);
            int c4 = (idx % (NCOLS / 4)) << 2;
            const float* srcp = (NCOLS == 64 || c4 < 64)
                              ? &Wa[(k0 + k) * 64 + c4]
                              : &Wb[(k0 + k) * 64 + c4 - 64];
            float4 v = *(const float4*)srcp;
            uint4 h, l;
            h.x = f2tf32(v.x); l.x = f2tf32(v.x - __uint_as_float(h.x));
            h.y = f2tf32(v.y); l.y = f2tf32(v.y - __uint_as_float(h.y));
            h.z = f2tf32(v.z); l.z = f2tf32(v.z - __uint_as_float(h.z));
            h.w = f2tf32(v.w); l.w = f2tf32(v.w - __uint_as_float(h.w));
            *(uint4*)&Wh[k * WSTR + c4] = h;
            *(uint4*)&Wl[k * WSTR + c4] = l;
        }
        __syncthreads();

        #pragma unroll
        for (int kk = 0; kk < 4; kk++) {
            unsigned ah[2][4], al_[2][4];
            #pragma unroll
            for (int i = 0; i < 2; i++) {
                int rb = wm * 32 + 16 * i;
                int c0 = kk * 8 + tig;
                ah[i][0] = Xh[(rb + g) * XSTR + c0];
                ah[i][1] = Xh[(rb + g + 8) * XSTR + c0];
                ah[i][2] = Xh[(rb + g) * XSTR + c0 + 4];
                ah[i][3] = Xh[(rb + g + 8) * XSTR + c0 + 4];
                al_[i][0] = Xl[(rb + g) * XSTR + c0];
                al_[i][1] = Xl[(rb + g + 8) * XSTR + c0];
                al_[i][2] = Xl[(rb + g) * XSTR + c0 + 4];
                al_[i][3] = Xl[(rb + g + 8) * XSTR + c0 + 4];
            }
            #pragma unroll
            for (int j = 0; j < 8; j++) {
                int col = wn * 64 + j * 8 + g;
                int kr = kk * 8 + tig;
                unsigned bh0 = Wh[kr * WSTR + col];
                unsigned bh1 = Wh[(kr + 4) * WSTR + col];
                unsigned bl0 = Wl[kr * WSTR + col];
                unsigned bl1 = Wl[(kr + 4) * WSTR + col];
                #pragma unroll
                for (int i = 0; i < 2; i++) {
                    mma_tf32(acc[i][j], ah[i],  bh0, bh1);
                    mma_tf32(acc[i][j], al_[i], bh0, bh1);
                    mma_tf32(acc[i][j], ah[i],  bl0, bl1);
                }
            }
        }
        __syncthreads();
    }

    #pragma unroll
    for (int i = 0; i < 2; i++) {
        #pragma unroll
        for (int j = 0; j < 8; j++) {
            int row = row0 + wm * 32 + 16 * i + g;
            int col = wn * 64 + j * 8 + 2 * tig;
            bool toB = (NCOLS == 128 && col >= 64);
            float* outp = toB ? Cb : Ca;
            int c = toB ? col - 64 : col;
            if (row < n) {
                *(float2*)&outp[row * 64 + c] = make_float2(acc[i][j][0], acc[i][j][1]);
                if (!toB) *(__half2*)&Ch[row * 64 + c] = __floats2half2_rn(acc[i][j][0], acc[i][j][1]);
            }
            if (row + 8 < n) {
                *(float2*)&outp[(row + 8) * 64 + c] = make_float2(acc[i][j][2], acc[i][j][3]);
                if (!toB) *(__half2*)&Ch[(row + 8) * 64 + c] = __floats2half2_rn(acc[i][j][2], acc[i][j][3]);
            }
        }
    }
}

// =================== per-node attention logits ==============================
__global__ void compute_elr(const float* __restrict__ feat,
                            const float* __restrict__ al, const float* __restrict__ ar,
                            float* __restrict__ el, float* __restrict__ er) {
    int i = blockIdx.x * blockDim.x + threadIdx.x;   // n*4 + h
    if (i >= NN * 4) return;
    int h = i & 3;
    int n = i >> 2;
    const float4* f = (const float4*)(feat + n * 64 + h * 16);
    const float4* a = (const float4*)(al + h * 16);
    const float4* b = (const float4*)(ar + h * 16);
    float s1 = 0.f, s2 = 0.f;
    #pragma unroll
    for (int j = 0; j < 4; j++) {
        float4 fv = f[j], av = __ldg(a + j), bv = __ldg(b + j);
        s1 += fv.x * av.x + fv.y * av.y + fv.z * av.z + fv.w * av.w;
        s2 += fv.x * bv.x + fv.y * bv.y + fv.z * bv.z + fv.w * bv.w;
    }
    el[i] = s1;
    er[i] = s2;
}

// =================== fused single-pass aggregation ==========================
// 8 threads per node; thread j handles 8 halfs (one uint4), head h = j>>1.
// 2-edge manual unroll for MLP.

__device__ __forceinline__ void acc8(float* acc, uint4 raw, float ee) {
    float2 p;
    p = __half22float2(*(const __half2*)&raw.x); acc[0] += ee * p.x; acc[1] += ee * p.y;
    p = __half22float2(*(const __half2*)&raw.y); acc[2] += ee * p.x; acc[3] += ee * p.y;
    p = __half22float2(*(const __half2*)&raw.z); acc[4] += ee * p.x; acc[5] += ee * p.y;
    p = __half22float2(*(const __half2*)&raw.w); acc[6] += ee * p.x; acc[7] += ee * p.y;
}

template<int LAYER>
__global__ void __launch_bounds__(256) agg_fused(
        const int* __restrict__ start, const int* __restrict__ cnt,
        const int* __restrict__ csrc,
        const float* __restrict__ el, const float* __restrict__ er,
        const __half* __restrict__ feath, const float* __restrict__ res,
        const float* __restrict__ bias, float* __restrict__ outp) {
    int gid = blockIdx.x * 256 + threadIdx.x;
    int node = gid >> 3;
    if (node >= NN) return;
    int j = gid & 7;
    int h = j >> 1;
    float ern = __ldg(er + node * 4 + h);
    int beg = __ldg(start + node);
    int end = beg + __ldg(cnt + node);

    float den = 0.f;
    float acc[8] = {};

    int k = beg;
    for (; k + 2 <= end; k += 2) {
        int s0 = __ldg(csrc + k);
        int s1 = __ldg(csrc + k + 1);
        float e0 = __ldg(el + s0 * 4 + h);
        float e1 = __ldg(el + s1 * 4 + h);
        uint4 r0 = __ldg((const uint4*)(feath + s0 * 64 + j * 8));
        uint4 r1 = __ldg((const uint4*)(feath + s1 * 64 + j * 8));
        e0 += ern; e0 = (e0 > 0.f) ? e0 : 0.2f * e0;
        e1 += ern; e1 = (e1 > 0.f) ? e1 : 0.2f * e1;
        float w0 = __expf(e0), w1 = __expf(e1);
        den += w0 + w1;
        acc8(acc, r0, w0);
        acc8(acc, r1, w1);
    }
    if (k < end) {
        int s0 = __ldg(csrc + k);
        float e0 = __ldg(el + s0 * 4 + h) + ern;
        e0 = (e0 > 0.f) ? e0 : 0.2f * e0;
        float w0 = __expf(e0);
        den += w0;
        uint4 r0 = __ldg((const uint4*)(feath + s0 * 64 + j * 8));
        acc8(acc, r0, w0);
    }

    float r = (den > 0.f) ? (1.f / den) : 0.f;
    float o[8];
    const float4 rs0 = *(const float4*)(res + node * 64 + j * 8);
    const float4 rs1 = *(const float4*)(res + node * 64 + j * 8 + 4);
    const float4 bb0 = __ldg((const float4*)(bias + j * 8));
    const float4 bb1 = __ldg((const float4*)(bias + j * 8 + 4));
    o[0] = acc[0] * r + rs0.x + bb0.x;
    o[1] = acc[1] * r + rs0.y + bb0.y;
    o[2] = acc[2] * r + rs0.z + bb0.z;
    o[3] = acc[3] * r + rs0.w + bb0.w;
    o[4] = acc[4] * r + rs1.x + bb1.x;
    o[5] = acc[5] * r + rs1.y + bb1.y;
    o[6] = acc[6] * r + rs1.z + bb1.z;
    o[7] = acc[7] * r + rs1.w + bb1.w;

    if (LAYER == 1) {
        #pragma unroll
        for (int c = 0; c < 8; c++) o[c] = (o[c] > 0.f) ? o[c] : expm1f(o[c]);
        *(float4*)(outp + node * 64 + j * 8)     = make_float4(o[0], o[1], o[2], o[3]);
        *(float4*)(outp + node * 64 + j * 8 + 4) = make_float4(o[4], o[5], o[6], o[7]);
    } else {
        // mean over 4 heads: lanes j, j^2, j^4 hold the same output slot dd=(j&1)*8+c
        #pragma unroll
        for (int c = 0; c < 8; c++) {
            o[c] += __shfl_xor_sync(~0u, o[c], 2);
            o[c] += __shfl_xor_sync(~0u, o[c], 4);
            o[c] *= 0.25f;
        }
        if (j < 2) {
            *(float4*)(outp + node * 16 + j * 8)     = make_float4(o[0], o[1], o[2], o[3]);
            *(float4*)(outp + node * 16 + j * 8 + 4) = make_float4(o[4], o[5], o[6], o[7]);
        }
    }
}

// =================== launch ==================================================
extern "C" void kernel_launch(void* const* d_in, const int* in_sizes, int n_in,
                              void* d_out, int out_size) {
    const float* x     = (const float*)d_in[0];
    const int*   src   = (const int*)  d_in[1];
    const int*   dst   = (const int*)  d_in[2];
    const float* W1    = (const float*)d_in[3];
    const float* al1   = (const float*)d_in[4];
    const float* ar1   = (const float*)d_in[5];
    const float* resW1 = (const float*)d_in[6];
    const float* b1    = (const float*)d_in[7];
    const float* W2    = (const float*)d_in[8];
    const float* al2   = (const float*)d_in[9];
    const float* ar2   = (const float*)d_in[10];
    const float* b2    = (const float*)d_in[11];
    float* out = (float*)d_out;

    float *feat, *res1, *h1, *el, *er;
    __half* feath;
    int *cnt, *start, *cursor, *csrc, *total;
    cudaGetSymbolAddress((void**)&feat,   g_feat);
    cudaGetSymbolAddress((void**)&feath,  g_feath);
    cudaGetSymbolAddress((void**)&res1,   g_res1);
    cudaGetSymbolAddress((void**)&h1,     g_h1);
    cudaGetSymbolAddress((void**)&el,     g_el);
    cudaGetSymbolAddress((void**)&er,     g_er);
    cudaGetSymbolAddress((void**)&cnt,    g_cnt);
    cudaGetSymbolAddress((void**)&start,  g_start);
    cudaGetSymbolAddress((void**)&cursor, g_cursor);
    cudaGetSymbolAddress((void**)&csrc,   g_csrc);
    cudaGetSymbolAddress((void**)&total,  g_total);

    static cudaStream_t s2 = nullptr;
    static cudaEvent_t evFork = nullptr, evJoin = nullptr;
    if (s2 == nullptr) {
        cudaStreamCreateWithFlags(&s2, cudaStreamNonBlocking);
        cudaEventCreateWithFlags(&evFork, cudaEventDisableTiming);
        cudaEventCreateWithFlags(&evJoin, cudaEventDisableTiming);
    }

    const int T = 256;
    const int edgeBlocks = (EE + T - 1) / T;
    const int gemmBlocks = (NN + 127) / 128;
    const int elrBlocks  = (NN * 4 + T - 1) / T;
    const int aggBlocks  = (NN * 8 + T - 1) / T;
    const int nodeBlocks = (NN + T - 1) / T;

    const int smem128 = (2 * 128 * 36 + 2 * 32 * 136) * 4;
    const int smem64  = (2 * 128 * 36 + 2 * 32 * 72) * 4;
    cudaFuncSetAttribute(gemm_tc<128>, cudaFuncAttributeMaxDynamicSharedMemorySize, smem128);
    cudaFuncSetAttribute(gemm_tc<64>,  cudaFuncAttributeMaxDynamicSharedMemorySize, smem64);

    // ---- fork: CSR build on s2, GEMM+elr on main ----
    cudaEventRecord(evFork, 0);
    cudaStreamWaitEvent(s2, evFork, 0);

    zero_cnt<<<nodeBlocks, T, 0, s2>>>(cnt, total);
    hist_dst<<<edgeBlocks, T, 0, s2>>>(dst, cnt);
    alloc_seg<<<nodeBlocks, T, 0, s2>>>(cnt, start, cursor, total);
    scatter_edges<<<edgeBlocks, T, 0, s2>>>(src, dst, cursor, csrc);
    cudaEventRecord(evJoin, s2);

    gemm_tc<128><<<gemmBlocks, 256, smem128>>>(x, W1, resW1, feat, res1, feath, NN, 128);
    compute_elr<<<elrBlocks, T>>>(feat, al1, ar1, el, er);

    cudaStreamWaitEvent(0, evJoin, 0);

    agg_fused<1><<<aggBlocks, T>>>(start, cnt, csrc, el, er, feath, res1, b1, h1);

    // ---- layer 2 ----
    gemm_tc<64><<<gemmBlocks, 128, smem64>>>(h1, W2, nullptr, feat, nullptr, feath, NN, 64);
    compute_elr<<<elrBlocks, T>>>(feat, al2, ar2, el, er);
    agg_fused<2><<<aggBlocks, T>>>(start, cnt, csrc, el, er, feath, h1, b2, out);
}